// round 16
// baseline (speedup 1.0000x reference)
#include <cuda_runtime.h>
#include <cuda_fp16.h>
#include <stdint.h>
#include <math.h>

// ---------------------------------------------------------------------------
// Problem constants
// ---------------------------------------------------------------------------
#define N_EMBD 2048
#define NH     16
#define HD     128
#define TT     2048
#define BB     2
#define MROWS  (BB * TT)
#define QKV_N  (3 * N_EMBD)

// ---------------------------------------------------------------------------
// Scratch
// ---------------------------------------------------------------------------
__device__ float g_cos[TT * (HD / 2)];
__device__ float g_sin[TT * (HD / 2)];
__device__ __half g_A [(size_t)MROWS * N_EMBD];   // x (single), later y (single)
__device__ __half g_Wa[(size_t)QKV_N * N_EMBD];
__device__ __half g_Wp[(size_t)N_EMBD * N_EMBD];
__device__ __half g_Q [(size_t)MROWS * N_EMBD];   // roped q
__device__ __half g_K [(size_t)MROWS * N_EMBD];   // roped k
__device__ __half g_Vh[(size_t)MROWS * N_EMBD];   // v row-major
__device__ __half g_Vt[(size_t)MROWS * N_EMBD];   // V^T per head [bh][d][t]

// ---------------------------------------------------------------------------
// Helpers
// ---------------------------------------------------------------------------
__device__ __forceinline__ uint32_t smem_u32(const void* p) {
    uint32_t a;
    asm("{ .reg .u64 t; cvta.to.shared.u64 t, %1; cvt.u32.u64 %0, t; }"
        : "=r"(a) : "l"(p));
    return a;
}

__device__ __forceinline__ void ldsm_x4(uint32_t* r, uint32_t addr) {
    asm volatile("ldmatrix.sync.aligned.m8n8.x4.shared.b16 {%0,%1,%2,%3}, [%4];"
                 : "=r"(r[0]), "=r"(r[1]), "=r"(r[2]), "=r"(r[3]) : "r"(addr));
}

__device__ __forceinline__ void mma16816(float* c, const uint32_t* a,
                                         const uint32_t* b) {
    asm volatile(
        "mma.sync.aligned.m16n8k16.row.col.f32.f16.f16.f32 "
        "{%0,%1,%2,%3}, {%4,%5,%6,%7}, {%8,%9}, {%0,%1,%2,%3};"
        : "+f"(c[0]), "+f"(c[1]), "+f"(c[2]), "+f"(c[3])
        : "r"(a[0]), "r"(a[1]), "r"(a[2]), "r"(a[3]), "r"(b[0]), "r"(b[1]));
}

#define CP_ASYNC16(dst, src) \
    asm volatile("cp.async.cg.shared.global [%0], [%1], 16;" \
                 :: "r"(dst), "l"(src) : "memory")
#define CP_COMMIT() asm volatile("cp.async.commit_group;" ::: "memory")
#define CP_WAIT1()  asm volatile("cp.async.wait_group 1;" ::: "memory")

__device__ __forceinline__ uint32_t pack_h(float x, float y) {
    __half2 hh = __floats2half2_rn(x, y);
    return *(uint32_t*)&hh;
}

// ---------------------------------------------------------------------------
// Convert kernels
// ---------------------------------------------------------------------------
__global__ void conv_single_kernel(const float* __restrict__ in,
                                   __half* __restrict__ o, int n4) {
    int idx = blockIdx.x * blockDim.x + threadIdx.x;
    if (idx >= n4) return;
    float4 v = ((const float4*)in)[idx];
    ((__half2*)o)[idx * 2]     = __floats2half2_rn(v.x, v.y);
    ((__half2*)o)[idx * 2 + 1] = __floats2half2_rn(v.z, v.w);
}

__global__ void conv_tr_kernel(const float* __restrict__ B,
                               __half* __restrict__ bt, int K, int N) {
    __shared__ float tile[32][33];
    int n0 = blockIdx.x * 32, k0 = blockIdx.y * 32;
    int tx = threadIdx.x, ty = threadIdx.y;
#pragma unroll
    for (int i = 0; i < 4; i++)
        tile[ty + i * 8][tx] = B[(size_t)(k0 + ty + i * 8) * N + n0 + tx];
    __syncthreads();
#pragma unroll
    for (int i = 0; i < 4; i++) {
        int n = ty + i * 8;
        bt[(size_t)(n0 + n) * K + k0 + tx] = __float2half_rn(tile[tx][n]);
    }
}

__global__ void conv_vth_kernel(const __half* __restrict__ vh,
                                __half* __restrict__ vt) {
    __shared__ __half tile[32][34];
    int bh = blockIdx.z;
    int b = bh >> 4, h = bh & 15;
    int t0 = blockIdx.x * 32, d0 = blockIdx.y * 32;
    int tx = threadIdx.x, ty = threadIdx.y;
#pragma unroll
    for (int i = 0; i < 4; i++)
        tile[ty + i * 8][tx] =
            vh[(size_t)(b * TT + t0 + ty + i * 8) * N_EMBD + h * HD + d0 + tx];
    __syncthreads();
#pragma unroll
    for (int i = 0; i < 4; i++) {
        int d = ty + i * 8;
        vt[(size_t)(bh * HD + d0 + d) * TT + t0 + tx] = tile[tx][d];
    }
}

__global__ void rope_table_kernel() {
    int idx = blockIdx.x * blockDim.x + threadIdx.x;
    if (idx >= TT * 64) return;
    int t = idx >> 6;
    int i = idx & 63;
    double theta = pow(10000.0, -(double)i / 64.0);
    double ang = (double)t * theta;
    g_cos[idx] = (float)cos(ang);
    g_sin[idx] = (float)sin(ang);
}

// ---------------------------------------------------------------------------
// GEMM config (single-fp16 A)
// ---------------------------------------------------------------------------
#define BM 128
#define BK 32
#define PADB 80
#define A_BYTES (128 * PADB)

#define BN6 192
#define B6_BYTES (192 * PADB)
#define STG6 (A_BYTES + B6_BYTES)
#define QKV_SMEM (2 * STG6)

#define BN4 256
#define B4_BYTES (256 * PADB)
#define STG4 (A_BYTES + B4_BYTES)
#define PROJ_SMEM (2 * STG4)

// ---------------------------------------------------------------------------
// QKV GEMM (BN=192, single-term) with fused RoPE/convert epilogue.
// ---------------------------------------------------------------------------
__global__ __launch_bounds__(256, 1) void gemm_qkv_kernel(
    const __half* __restrict__ A, const __half* __restrict__ B,
    __half* __restrict__ Q, __half* __restrict__ Kb, __half* __restrict__ Vh)
{
    const int K = N_EMBD;
    extern __shared__ char smc[];
    const uint32_t sbase = smem_u32(smc);
    const int tid = threadIdx.x;
    const int lane = tid & 31;
    const int wid = tid >> 5;
    const int wm = wid & 1;
    const int wn = wid >> 1;
    const int mBase = blockIdx.y * BM;
    const int nBase = blockIdx.x * BN6;
    const int nch = K / BK;

    const int ldRow = tid >> 2;
    const int ldCh  = tid & 3;

    float acc[4][6][4];
#pragma unroll
    for (int i = 0; i < 4; i++)
#pragma unroll
        for (int j = 0; j < 6; j++)
#pragma unroll
            for (int r = 0; r < 4; r++) acc[i][j][r] = 0.0f;

    auto issue_stage = [&](int c, int buf) {
        const uint32_t st = sbase + buf * STG6;
        const int kOff = c * BK;
#pragma unroll
        for (int i = 0; i < 2; i++) {
            const int row = i * 64 + ldRow;
            const uint32_t so = row * PADB + ldCh * 16;
            CP_ASYNC16(st + so,
                       A + (size_t)(mBase + row) * K + kOff + ldCh * 8);
        }
#pragma unroll
        for (int i = 0; i < 3; i++) {
            const int row = i * 64 + ldRow;
            const uint32_t so = row * PADB + ldCh * 16;
            CP_ASYNC16(st + A_BYTES + so,
                       B + (size_t)(nBase + row) * K + kOff + ldCh * 8);
        }
    };

    issue_stage(0, 0);
    CP_COMMIT();

    const int arow = (lane & 7) + ((lane >> 3) & 1) * 8;
    const int akc8 = (lane >> 4) * 8;
    const int brow = (lane & 7) + ((lane >> 4) & 1) * 8;
    const int bkc8 = ((lane >> 3) & 1) * 8;

    for (int c = 0; c < nch; c++) {
        const int buf = c & 1;
        if (c + 1 < nch) issue_stage(c + 1, (c + 1) & 1);
        CP_COMMIT();
        CP_WAIT1();
        __syncthreads();

        const uint32_t st = sbase + buf * STG6;
        const uint32_t aB = st;
        const uint32_t bB = st + A_BYTES;

#pragma unroll
        for (int s = 0; s < 2; s++) {
            const int kofs = s * 16;
            uint32_t af[4][4];
#pragma unroll
            for (int fm = 0; fm < 4; fm++) {
                const uint32_t off =
                    (uint32_t)((wm * 64 + fm * 16 + arow) * PADB +
                               (kofs + akc8) * 2);
                ldsm_x4(af[fm], aB + off);
            }
#pragma unroll
            for (int bi = 0; bi < 3; bi++) {
                uint32_t bf[4];
                const uint32_t off =
                    (uint32_t)((wn * 48 + bi * 16 + brow) * PADB +
                               (kofs + bkc8) * 2);
                ldsm_x4(bf, bB + off);
#pragma unroll
                for (int fm = 0; fm < 4; fm++) {
                    mma16816(acc[fm][2 * bi],     af[fm], bf);
                    mma16816(acc[fm][2 * bi + 1], af[fm], bf + 2);
                }
            }
        }
        __syncthreads();
    }

    const int r0 = lane >> 2;
    const int c0 = (lane & 3) * 2;
#pragma unroll
    for (int fm = 0; fm < 4; fm++) {
        const int row = mBase + wm * 64 + fm * 16 + r0;
        const int t0 = row & (TT - 1);
        const int t1 = (row + 8) & (TT - 1);
#pragma unroll
        for (int fn = 0; fn < 6; fn++) {
            const float v0 = acc[fm][fn][0], v1 = acc[fm][fn][1];
            const float v2 = acc[fm][fn][2], v3 = acc[fm][fn][3];
            const int col = nBase + wn * 48 + fn * 8 + c0;
            const int sec = col >> 11;
            const int cloc = col & (N_EMBD - 1);
            if (sec < 2) {
                const int i0 = (cloc & 127) >> 1;
                float cA = g_cos[t0 * 64 + i0], sA = g_sin[t0 * 64 + i0];
                float cB = g_cos[t1 * 64 + i0], sB = g_sin[t1 * 64 + i0];
                float r00 = v0 * cA - v1 * sA, r01 = v1 * cA + v0 * sA;
                float r10 = v2 * cB - v3 * sB, r11 = v3 * cB + v2 * sB;
                __half* dst = (sec == 0) ? Q : Kb;
                *(uint32_t*)(dst + (size_t)row * N_EMBD + cloc) =
                    pack_h(r00, r01);
                *(uint32_t*)(dst + (size_t)(row + 8) * N_EMBD + cloc) =
                    pack_h(r10, r11);
            } else {
                *(uint32_t*)(Vh + (size_t)row * N_EMBD + cloc) =
                    pack_h(v0, v1);
                *(uint32_t*)(Vh + (size_t)(row + 8) * N_EMBD + cloc) =
                    pack_h(v2, v3);
            }
        }
    }
}

// ---------------------------------------------------------------------------
// Proj GEMM (BN=256, single-term): fp32 out
// ---------------------------------------------------------------------------
__global__ __launch_bounds__(256, 1) void gemm_proj_kernel(
    const __half* __restrict__ A, const __half* __restrict__ B,
    float* __restrict__ C, int M, int N, int K)
{
    extern __shared__ char smc[];
    const uint32_t sbase = smem_u32(smc);
    const int tid = threadIdx.x;
    const int lane = tid & 31;
    const int wid = tid >> 5;
    const int wm = wid & 1;
    const int wn = wid >> 1;
    const int mBase = blockIdx.y * BM;
    const int nBase = blockIdx.x * BN4;
    const int nch = K / BK;

    const int ldRow = tid >> 2;
    const int ldCh  = tid & 3;

    float acc[4][8][4];
#pragma unroll
    for (int i = 0; i < 4; i++)
#pragma unroll
        for (int j = 0; j < 8; j++)
#pragma unroll
            for (int r = 0; r < 4; r++) acc[i][j][r] = 0.0f;

    auto issue_stage = [&](int c, int buf) {
        const uint32_t st = sbase + buf * STG4;
        const int kOff = c * BK;
#pragma unroll
        for (int i = 0; i < 2; i++) {
            const int row = i * 64 + ldRow;
            const uint32_t so = row * PADB + ldCh * 16;
            CP_ASYNC16(st + so,
                       A + (size_t)(mBase + row) * K + kOff + ldCh * 8);
        }
#pragma unroll
        for (int i = 0; i < 4; i++) {
            const int row = i * 64 + ldRow;
            const uint32_t so = row * PADB + ldCh * 16;
            CP_ASYNC16(st + A_BYTES + so,
                       B + (size_t)(nBase + row) * K + kOff + ldCh * 8);
        }
    };

    issue_stage(0, 0);
    CP_COMMIT();

    const int arow = (lane & 7) + ((lane >> 3) & 1) * 8;
    const int akc8 = (lane >> 4) * 8;
    const int brow = (lane & 7) + ((lane >> 4) & 1) * 8;
    const int bkc8 = ((lane >> 3) & 1) * 8;

    for (int c = 0; c < nch; c++) {
        const int buf = c & 1;
        if (c + 1 < nch) issue_stage(c + 1, (c + 1) & 1);
        CP_COMMIT();
        CP_WAIT1();
        __syncthreads();

        const uint32_t st = sbase + buf * STG4;
        const uint32_t aB = st;
        const uint32_t bB = st + A_BYTES;

#pragma unroll
        for (int s = 0; s < 2; s++) {
            const int kofs = s * 16;
            uint32_t af[4][4];
#pragma unroll
            for (int fm = 0; fm < 4; fm++) {
                const uint32_t off =
                    (uint32_t)((wm * 64 + fm * 16 + arow) * PADB +
                               (kofs + akc8) * 2);
                ldsm_x4(af[fm], aB + off);
            }
#pragma unroll
            for (int bi = 0; bi < 4; bi++) {
                uint32_t bf[4];
                const uint32_t off =
                    (uint32_t)((wn * 64 + bi * 16 + brow) * PADB +
                               (kofs + bkc8) * 2);
                ldsm_x4(bf, bB + off);
#pragma unroll
                for (int fm = 0; fm < 4; fm++) {
                    mma16816(acc[fm][2 * bi],     af[fm], bf);
                    mma16816(acc[fm][2 * bi + 1], af[fm], bf + 2);
                }
            }
        }
        __syncthreads();
    }

    const int r0 = lane >> 2;
    const int c0 = (lane & 3) * 2;
#pragma unroll
    for (int fm = 0; fm < 4; fm++) {
#pragma unroll
        for (int fn = 0; fn < 8; fn++) {
            const size_t row = (size_t)(mBase + wm * 64 + fm * 16 + r0);
            const int col = nBase + wn * 64 + fn * 8 + c0;
            *(float2*)(C + row * N + col) =
                make_float2(acc[fm][fn][0], acc[fm][fn][1]);
            *(float2*)(C + (row + 8) * N + col) =
                make_float2(acc[fm][fn][2], acc[fm][fn][3]);
        }
    }
}

// ---------------------------------------------------------------------------
// Flash attention: single fp16, SOFTWARE-PIPELINED — S(c+1) MMAs issue
// before softmax(c)+PV(c) so the tensor pipe stays busy during softmax.
// 3-stage cp.async ring (stage c's V stays live while c+2 loads).
// ---------------------------------------------------------------------------
#define FQ_BYTES   (128 * 272)
#define FK_BYTES   (64 * 272)
#define FV_BYTES   (128 * 144)
#define FSTAGE     (FK_BYTES + FV_BYTES)         // 35840
#define FA_SMEM    (FQ_BYTES + 3 * FSTAGE)       // 142336

__global__ __launch_bounds__(256, 1) void flash_mma_kernel(
    const __half* __restrict__ q, const __half* __restrict__ kh,
    const __half* __restrict__ vt, __half* __restrict__ y)
{
    extern __shared__ char smc[];
    const uint32_t sbase = smem_u32(smc);
    const int tid = threadIdx.x;
    const int lane = tid & 31;
    const int wid = tid >> 5;
    const int b = blockIdx.z, h = blockIdx.y;
    const int bh = b * NH + h;
    const int q0 = blockIdx.x * 128;
    const size_t bT = (size_t)b * TT;
    const int hoff = h * HD;

    // Q load (group 0)
    {
#pragma unroll
        for (int i = 0; i < 8; i++) {
            int cid = i * 256 + tid;
            int row = cid >> 4, ch = cid & 15;
            CP_ASYNC16(sbase + row * 272 + ch * 16,
                       q + (bT + q0 + row) * N_EMBD + hoff + ch * 8);
        }
        CP_COMMIT();
    }

    auto issue_stage = [&](int it, int buf) {
        const uint32_t st = sbase + FQ_BYTES + buf * FSTAGE;
        const int n0 = it * 64;
#pragma unroll
        for (int i = 0; i < 4; i++) {
            int cid = i * 256 + tid;
            int row = cid >> 4, ch = cid & 15;
            CP_ASYNC16(st + row * 272 + ch * 16,
                       kh + (bT + n0 + row) * N_EMBD + hoff + ch * 8);
        }
#pragma unroll
        for (int i = 0; i < 4; i++) {
            int cid = i * 256 + tid;
            int row = cid >> 3, ch = cid & 7;
            CP_ASYNC16(st + FK_BYTES + row * 144 + ch * 16,
                       vt + (size_t)(bh * HD + row) * TT + n0 + ch * 8);
        }
    };

    issue_stage(0, 0);
    CP_COMMIT();
    issue_stage(1, 1);
    CP_COMMIT();

    const int arow = (lane & 7) + ((lane >> 3) & 1) * 8;
    const int aoff = (lane >> 4) * 16;
    const int brow = (lane & 7) + ((lane >> 4) & 1) * 8;
    const int boff = ((lane >> 3) & 1) * 16;
    const int g = lane >> 2;
    const int tq = lane & 3;

    // S computation from a given K stage buffer
    auto compute_S = [&](float (*sA)[4], uint32_t kb) {
#pragma unroll
        for (int kk = 0; kk < 8; kk++) {
            uint32_t qf[4];
            const uint32_t qo = (wid * 16 + arow) * 272 + kk * 32 + aoff;
            ldsm_x4(qf, sbase + qo);
#pragma unroll
            for (int bp = 0; bp < 2; bp++) {
                uint32_t khf[2][4];
#pragma unroll
                for (int u = 0; u < 2; u++) {
                    const int bi = 2 * bp + u;
                    const uint32_t ko = (bi * 16 + brow) * 272 + kk * 32 + boff;
                    ldsm_x4(khf[u], kb + ko);
                }
#pragma unroll
                for (int u = 0; u < 2; u++) {
                    const int bi = 2 * bp + u;
                    mma16816(sA[2 * bi],     qf, khf[u]);
                    mma16816(sA[2 * bi + 1], qf, khf[u] + 2);
                }
            }
        }
    };

    float O[16][4];
#pragma unroll
    for (int i = 0; i < 16; i++)
#pragma unroll
        for (int r = 0; r < 4; r++) O[i][r] = 0.0f;
    float ma = -INFINITY, mb = -INFINITY, la = 0.0f, lb = 0.0f;
    const float sc = 0.08838834764831845f;

    const int niter = TT / 64;

    // Prologue: wait for Q + stage 0 (stage 1 may still be in flight)
    CP_WAIT1();
    __syncthreads();

    float s[8][4];
#pragma unroll
    for (int j = 0; j < 8; j++)
#pragma unroll
        for (int r = 0; r < 4; r++) s[j][r] = 0.0f;
    compute_S(s, sbase + FQ_BYTES);   // S(0) from buf 0

    for (int c = 0; c < niter; c++) {
        // issue stage c+2 into buf (c+2)%3 (V(c-1) reads finished last iter)
        if (c + 2 < niter) issue_stage(c + 2, (c + 2) % 3);
        CP_COMMIT();
        CP_WAIT1();           // stage c+1 complete (only c+2 may pend)
        __syncthreads();

        // ---- prefetch S(c+1) into s2 (tensor pipe busy during softmax) ----
        float s2[8][4];
        if (c + 1 < niter) {
#pragma unroll
            for (int j = 0; j < 8; j++)
#pragma unroll
                for (int r = 0; r < 4; r++) s2[j][r] = 0.0f;
            compute_S(s2, sbase + FQ_BYTES + ((c + 1) % 3) * FSTAGE);
        }

        // ---- softmax on s (tile c) ----
        float mxa = -INFINITY, mxb = -INFINITY;
#pragma unroll
        for (int j = 0; j < 8; j++) {
            s[j][0] *= sc; s[j][1] *= sc; s[j][2] *= sc; s[j][3] *= sc;
            mxa = fmaxf(mxa, fmaxf(s[j][0], s[j][1]));
            mxb = fmaxf(mxb, fmaxf(s[j][2], s[j][3]));
        }
        mxa = fmaxf(mxa, __shfl_xor_sync(0xffffffffu, mxa, 1));
        mxa = fmaxf(mxa, __shfl_xor_sync(0xffffffffu, mxa, 2));
        mxb = fmaxf(mxb, __shfl_xor_sync(0xffffffffu, mxb, 1));
        mxb = fmaxf(mxb, __shfl_xor_sync(0xffffffffu, mxb, 2));
        float mna = fmaxf(ma, mxa), mnb = fmaxf(mb, mxb);
        float alpha = __expf(ma - mna), beta = __expf(mb - mnb);
        ma = mna; mb = mnb;
        float sua = 0.0f, sub = 0.0f;
#pragma unroll
        for (int j = 0; j < 8; j++) {
            s[j][0] = __expf(s[j][0] - mna);
            s[j][1] = __expf(s[j][1] - mna);
            s[j][2] = __expf(s[j][2] - mnb);
            s[j][3] = __expf(s[j][3] - mnb);
            sua += s[j][0] + s[j][1];
            sub += s[j][2] + s[j][3];
        }
        sua += __shfl_xor_sync(0xffffffffu, sua, 1);
        sua += __shfl_xor_sync(0xffffffffu, sua, 2);
        sub += __shfl_xor_sync(0xffffffffu, sub, 1);
        sub += __shfl_xor_sync(0xffffffffu, sub, 2);
        la = la * alpha + sua;
        lb = lb * beta + sub;
#pragma unroll
        for (int j2 = 0; j2 < 16; j2++) {
            O[j2][0] *= alpha; O[j2][1] *= alpha;
            O[j2][2] *= beta;  O[j2][3] *= beta;
        }

        uint32_t Ph[4][4];
#pragma unroll
        for (int kp = 0; kp < 4; kp++) {
            Ph[kp][0] = pack_h(s[2 * kp][0],     s[2 * kp][1]);
            Ph[kp][1] = pack_h(s[2 * kp][2],     s[2 * kp][3]);
            Ph[kp][2] = pack_h(s[2 * kp + 1][0], s[2 * kp + 1][1]);
            Ph[kp][3] = pack_h(s[2 * kp + 1][2], s[2 * kp + 1][3]);
        }

        // ---- O += P @ V from stage c's V ----
        const uint32_t vb = sbase + FQ_BYTES + (c % 3) * FSTAGE + FK_BYTES;
#pragma unroll
        for (int kp = 0; kp < 4; kp++) {
#pragma unroll
            for (int jp = 0; jp < 4; jp++) {
                uint32_t vhf[2][4];
#pragma unroll
                for (int u = 0; u < 2; u++) {
                    const int j4 = 2 * jp + u;
                    const uint32_t vo = (j4 * 16 + brow) * 144 + kp * 32 + boff;
                    ldsm_x4(vhf[u], vb + vo);
                }
#pragma unroll
                for (int u = 0; u < 2; u++) {
                    const int j4 = 2 * jp + u;
                    mma16816(O[2 * j4],     Ph[kp], vhf[u]);
                    mma16816(O[2 * j4 + 1], Ph[kp], vhf[u] + 2);
                }
            }
        }

        // carry prefetched S
        if (c + 1 < niter) {
#pragma unroll
            for (int j = 0; j < 8; j++)
#pragma unroll
                for (int r = 0; r < 4; r++) s[j][r] = s2[j][r];
        }
        __syncthreads();   // all warps done with stage c's V before reuse
    }

    // ---- epilogue: normalize + single fp16 write into g_A (proj input) ----
    const float inva = 1.0f / la, invb = 1.0f / lb;
    const size_t rowa = bT + q0 + wid * 16 + g;
    const size_t rowb = rowa + 8;
#pragma unroll
    for (int j2 = 0; j2 < 16; j2++) {
        const int col = hoff + j2 * 8 + tq * 2;
        *(uint32_t*)(y + rowa * N_EMBD + col) =
            pack_h(O[j2][0] * inva, O[j2][1] * inva);
        *(uint32_t*)(y + rowb * N_EMBD + col) =
            pack_h(O[j2][2] * invb, O[j2][3] * invb);
    }
}

// ---------------------------------------------------------------------------
// Launch
// ---------------------------------------------------------------------------
extern "C" void kernel_launch(void* const* d_in, const int* in_sizes, int n_in,
                              void* d_out, int out_size)
{
    const float* x      = (const float*)d_in[0];
    const float* w_attn = (const float*)d_in[1];
    const float* w_proj = (const float*)d_in[2];
    float* out = (float*)d_out;

    __half *A, *Wa, *Wp, *Q, *Kb, *Vh, *Vt;
    cudaGetSymbolAddress((void**)&A, g_A);
    cudaGetSymbolAddress((void**)&Wa, g_Wa);
    cudaGetSymbolAddress((void**)&Wp, g_Wp);
    cudaGetSymbolAddress((void**)&Q, g_Q);
    cudaGetSymbolAddress((void**)&Kb, g_K);
    cudaGetSymbolAddress((void**)&Vh, g_Vh);
    cudaGetSymbolAddress((void**)&Vt, g_Vt);

    cudaFuncSetAttribute(gemm_qkv_kernel,
                         cudaFuncAttributeMaxDynamicSharedMemorySize, QKV_SMEM);
    cudaFuncSetAttribute(gemm_proj_kernel,
                         cudaFuncAttributeMaxDynamicSharedMemorySize, PROJ_SMEM);
    cudaFuncSetAttribute(flash_mma_kernel,
                         cudaFuncAttributeMaxDynamicSharedMemorySize, FA_SMEM);

    const int n4 = MROWS * N_EMBD / 4;

    rope_table_kernel<<<(TT * 64 + 255) / 256, 256>>>();

    conv_single_kernel<<<(n4 + 255) / 256, 256>>>(x, A, n4);
    conv_tr_kernel<<<dim3(QKV_N / 32, N_EMBD / 32), dim3(32, 8)>>>(
        w_attn, Wa, N_EMBD, QKV_N);
    conv_tr_kernel<<<dim3(N_EMBD / 32, N_EMBD / 32), dim3(32, 8)>>>(
        w_proj, Wp, N_EMBD, N_EMBD);

    gemm_qkv_kernel<<<dim3(QKV_N / BN6, MROWS / BM), 256, QKV_SMEM>>>(
        A, Wa, Q, Kb, Vh);

    conv_vth_kernel<<<dim3(TT / 32, HD / 32, BB * NH), dim3(32, 8)>>>(Vh, Vt);

    flash_mma_kernel<<<dim3(TT / 128, NH, BB), 256, FA_SMEM>>>(
        Q, Kb, Vt, A);

    gemm_proj_kernel<<<dim3(N_EMBD / BN4, MROWS / BM), 256, PROJ_SMEM>>>(
        A, Wp, out, MROWS, N_EMBD, N_EMBD);
}

// round 17
// speedup vs baseline: 1.0448x; 1.0448x over previous
#include <cuda_runtime.h>
#include <cuda_fp16.h>
#include <stdint.h>
#include <math.h>

// ---------------------------------------------------------------------------
// Problem constants
// ---------------------------------------------------------------------------
#define N_EMBD 2048
#define NH     16
#define HD     128
#define TT     2048
#define BB     2
#define MROWS  (BB * TT)
#define QKV_N  (3 * N_EMBD)

// ---------------------------------------------------------------------------
// Scratch
// ---------------------------------------------------------------------------
__device__ float g_cos[TT * (HD / 2)];
__device__ float g_sin[TT * (HD / 2)];
__device__ __half g_A [(size_t)MROWS * N_EMBD];   // x (single), later y (single)
__device__ __half g_Wa[(size_t)QKV_N * N_EMBD];
__device__ __half g_Wp[(size_t)N_EMBD * N_EMBD];
__device__ __half g_Q [(size_t)MROWS * N_EMBD];   // roped q
__device__ __half g_K [(size_t)MROWS * N_EMBD];   // roped k
__device__ __half g_Vh[(size_t)MROWS * N_EMBD];   // v row-major
__device__ __half g_Vt[(size_t)MROWS * N_EMBD];   // V^T per head [bh][d][t]

// ---------------------------------------------------------------------------
// Helpers
// ---------------------------------------------------------------------------
__device__ __forceinline__ uint32_t smem_u32(const void* p) {
    uint32_t a;
    asm("{ .reg .u64 t; cvta.to.shared.u64 t, %1; cvt.u32.u64 %0, t; }"
        : "=r"(a) : "l"(p));
    return a;
}

__device__ __forceinline__ void ldsm_x4(uint32_t* r, uint32_t addr) {
    asm volatile("ldmatrix.sync.aligned.m8n8.x4.shared.b16 {%0,%1,%2,%3}, [%4];"
                 : "=r"(r[0]), "=r"(r[1]), "=r"(r[2]), "=r"(r[3]) : "r"(addr));
}

__device__ __forceinline__ void mma16816(float* c, const uint32_t* a,
                                         const uint32_t* b) {
    asm volatile(
        "mma.sync.aligned.m16n8k16.row.col.f32.f16.f16.f32 "
        "{%0,%1,%2,%3}, {%4,%5,%6,%7}, {%8,%9}, {%0,%1,%2,%3};"
        : "+f"(c[0]), "+f"(c[1]), "+f"(c[2]), "+f"(c[3])
        : "r"(a[0]), "r"(a[1]), "r"(a[2]), "r"(a[3]), "r"(b[0]), "r"(b[1]));
}

#define CP_ASYNC16(dst, src) \
    asm volatile("cp.async.cg.shared.global [%0], [%1], 16;" \
                 :: "r"(dst), "l"(src) : "memory")
#define CP_COMMIT() asm volatile("cp.async.commit_group;" ::: "memory")
#define CP_WAIT1()  asm volatile("cp.async.wait_group 1;" ::: "memory")

__device__ __forceinline__ uint32_t pack_h(float x, float y) {
    __half2 hh = __floats2half2_rn(x, y);
    return *(uint32_t*)&hh;
}

// ---------------------------------------------------------------------------
// Convert kernels
// ---------------------------------------------------------------------------
__global__ void conv_single_kernel(const float* __restrict__ in,
                                   __half* __restrict__ o, int n4) {
    int idx = blockIdx.x * blockDim.x + threadIdx.x;
    if (idx >= n4) return;
    float4 v = ((const float4*)in)[idx];
    ((__half2*)o)[idx * 2]     = __floats2half2_rn(v.x, v.y);
    ((__half2*)o)[idx * 2 + 1] = __floats2half2_rn(v.z, v.w);
}

__global__ void conv_tr_kernel(const float* __restrict__ B,
                               __half* __restrict__ bt, int K, int N) {
    __shared__ float tile[32][33];
    int n0 = blockIdx.x * 32, k0 = blockIdx.y * 32;
    int tx = threadIdx.x, ty = threadIdx.y;
#pragma unroll
    for (int i = 0; i < 4; i++)
        tile[ty + i * 8][tx] = B[(size_t)(k0 + ty + i * 8) * N + n0 + tx];
    __syncthreads();
#pragma unroll
    for (int i = 0; i < 4; i++) {
        int n = ty + i * 8;
        bt[(size_t)(n0 + n) * K + k0 + tx] = __float2half_rn(tile[tx][n]);
    }
}

__global__ void conv_vth_kernel(const __half* __restrict__ vh,
                                __half* __restrict__ vt) {
    __shared__ __half tile[32][34];
    int bh = blockIdx.z;
    int b = bh >> 4, h = bh & 15;
    int t0 = blockIdx.x * 32, d0 = blockIdx.y * 32;
    int tx = threadIdx.x, ty = threadIdx.y;
#pragma unroll
    for (int i = 0; i < 4; i++)
        tile[ty + i * 8][tx] =
            vh[(size_t)(b * TT + t0 + ty + i * 8) * N_EMBD + h * HD + d0 + tx];
    __syncthreads();
#pragma unroll
    for (int i = 0; i < 4; i++) {
        int d = ty + i * 8;
        vt[(size_t)(bh * HD + d0 + d) * TT + t0 + tx] = tile[tx][d];
    }
}

__global__ void rope_table_kernel() {
    int idx = blockIdx.x * blockDim.x + threadIdx.x;
    if (idx >= TT * 64) return;
    int t = idx >> 6;
    int i = idx & 63;
    double theta = pow(10000.0, -(double)i / 64.0);
    double ang = (double)t * theta;
    g_cos[idx] = (float)cos(ang);
    g_sin[idx] = (float)sin(ang);
}

// ---------------------------------------------------------------------------
// GEMM config (single-fp16 A)
// ---------------------------------------------------------------------------
#define BM 128
#define BK 32
#define PADB 80
#define A_BYTES (128 * PADB)

#define BN6 192
#define B6_BYTES (192 * PADB)
#define STG6 (A_BYTES + B6_BYTES)
#define QKV_SMEM (2 * STG6)

#define BN4 256
#define B4_BYTES (256 * PADB)
#define STG4 (A_BYTES + B4_BYTES)
#define PROJ_SMEM (2 * STG4)

// ---------------------------------------------------------------------------
// QKV GEMM (BN=192, single-term) with fused RoPE/convert epilogue.
// ---------------------------------------------------------------------------
__global__ __launch_bounds__(256, 1) void gemm_qkv_kernel(
    const __half* __restrict__ A, const __half* __restrict__ B,
    __half* __restrict__ Q, __half* __restrict__ Kb, __half* __restrict__ Vh)
{
    const int K = N_EMBD;
    extern __shared__ char smc[];
    const uint32_t sbase = smem_u32(smc);
    const int tid = threadIdx.x;
    const int lane = tid & 31;
    const int wid = tid >> 5;
    const int wm = wid & 1;
    const int wn = wid >> 1;
    const int mBase = blockIdx.y * BM;
    const int nBase = blockIdx.x * BN6;
    const int nch = K / BK;

    const int ldRow = tid >> 2;
    const int ldCh  = tid & 3;

    float acc[4][6][4];
#pragma unroll
    for (int i = 0; i < 4; i++)
#pragma unroll
        for (int j = 0; j < 6; j++)
#pragma unroll
            for (int r = 0; r < 4; r++) acc[i][j][r] = 0.0f;

    auto issue_stage = [&](int c, int buf) {
        const uint32_t st = sbase + buf * STG6;
        const int kOff = c * BK;
#pragma unroll
        for (int i = 0; i < 2; i++) {
            const int row = i * 64 + ldRow;
            const uint32_t so = row * PADB + ldCh * 16;
            CP_ASYNC16(st + so,
                       A + (size_t)(mBase + row) * K + kOff + ldCh * 8);
        }
#pragma unroll
        for (int i = 0; i < 3; i++) {
            const int row = i * 64 + ldRow;
            const uint32_t so = row * PADB + ldCh * 16;
            CP_ASYNC16(st + A_BYTES + so,
                       B + (size_t)(nBase + row) * K + kOff + ldCh * 8);
        }
    };

    issue_stage(0, 0);
    CP_COMMIT();

    const int arow = (lane & 7) + ((lane >> 3) & 1) * 8;
    const int akc8 = (lane >> 4) * 8;
    const int brow = (lane & 7) + ((lane >> 4) & 1) * 8;
    const int bkc8 = ((lane >> 3) & 1) * 8;

    for (int c = 0; c < nch; c++) {
        const int buf = c & 1;
        if (c + 1 < nch) issue_stage(c + 1, (c + 1) & 1);
        CP_COMMIT();
        CP_WAIT1();
        __syncthreads();

        const uint32_t st = sbase + buf * STG6;
        const uint32_t aB = st;
        const uint32_t bB = st + A_BYTES;

#pragma unroll
        for (int s = 0; s < 2; s++) {
            const int kofs = s * 16;
            uint32_t af[4][4];
#pragma unroll
            for (int fm = 0; fm < 4; fm++) {
                const uint32_t off =
                    (uint32_t)((wm * 64 + fm * 16 + arow) * PADB +
                               (kofs + akc8) * 2);
                ldsm_x4(af[fm], aB + off);
            }
#pragma unroll
            for (int bi = 0; bi < 3; bi++) {
                uint32_t bf[4];
                const uint32_t off =
                    (uint32_t)((wn * 48 + bi * 16 + brow) * PADB +
                               (kofs + bkc8) * 2);
                ldsm_x4(bf, bB + off);
#pragma unroll
                for (int fm = 0; fm < 4; fm++) {
                    mma16816(acc[fm][2 * bi],     af[fm], bf);
                    mma16816(acc[fm][2 * bi + 1], af[fm], bf + 2);
                }
            }
        }
        __syncthreads();
    }

    const int r0 = lane >> 2;
    const int c0 = (lane & 3) * 2;
#pragma unroll
    for (int fm = 0; fm < 4; fm++) {
        const int row = mBase + wm * 64 + fm * 16 + r0;
        const int t0 = row & (TT - 1);
        const int t1 = (row + 8) & (TT - 1);
#pragma unroll
        for (int fn = 0; fn < 6; fn++) {
            const float v0 = acc[fm][fn][0], v1 = acc[fm][fn][1];
            const float v2 = acc[fm][fn][2], v3 = acc[fm][fn][3];
            const int col = nBase + wn * 48 + fn * 8 + c0;
            const int sec = col >> 11;
            const int cloc = col & (N_EMBD - 1);
            if (sec < 2) {
                const int i0 = (cloc & 127) >> 1;
                float cA = g_cos[t0 * 64 + i0], sA = g_sin[t0 * 64 + i0];
                float cB = g_cos[t1 * 64 + i0], sB = g_sin[t1 * 64 + i0];
                float r00 = v0 * cA - v1 * sA, r01 = v1 * cA + v0 * sA;
                float r10 = v2 * cB - v3 * sB, r11 = v3 * cB + v2 * sB;
                __half* dst = (sec == 0) ? Q : Kb;
                *(uint32_t*)(dst + (size_t)row * N_EMBD + cloc) =
                    pack_h(r00, r01);
                *(uint32_t*)(dst + (size_t)(row + 8) * N_EMBD + cloc) =
                    pack_h(r10, r11);
            } else {
                *(uint32_t*)(Vh + (size_t)row * N_EMBD + cloc) =
                    pack_h(v0, v1);
                *(uint32_t*)(Vh + (size_t)(row + 8) * N_EMBD + cloc) =
                    pack_h(v2, v3);
            }
        }
    }
}

// ---------------------------------------------------------------------------
// Proj GEMM (BN=256, single-term): fp32 out
// ---------------------------------------------------------------------------
__global__ __launch_bounds__(256, 1) void gemm_proj_kernel(
    const __half* __restrict__ A, const __half* __restrict__ B,
    float* __restrict__ C, int M, int N, int K)
{
    extern __shared__ char smc[];
    const uint32_t sbase = smem_u32(smc);
    const int tid = threadIdx.x;
    const int lane = tid & 31;
    const int wid = tid >> 5;
    const int wm = wid & 1;
    const int wn = wid >> 1;
    const int mBase = blockIdx.y * BM;
    const int nBase = blockIdx.x * BN4;
    const int nch = K / BK;

    const int ldRow = tid >> 2;
    const int ldCh  = tid & 3;

    float acc[4][8][4];
#pragma unroll
    for (int i = 0; i < 4; i++)
#pragma unroll
        for (int j = 0; j < 8; j++)
#pragma unroll
            for (int r = 0; r < 4; r++) acc[i][j][r] = 0.0f;

    auto issue_stage = [&](int c, int buf) {
        const uint32_t st = sbase + buf * STG4;
        const int kOff = c * BK;
#pragma unroll
        for (int i = 0; i < 2; i++) {
            const int row = i * 64 + ldRow;
            const uint32_t so = row * PADB + ldCh * 16;
            CP_ASYNC16(st + so,
                       A + (size_t)(mBase + row) * K + kOff + ldCh * 8);
        }
#pragma unroll
        for (int i = 0; i < 4; i++) {
            const int row = i * 64 + ldRow;
            const uint32_t so = row * PADB + ldCh * 16;
            CP_ASYNC16(st + A_BYTES + so,
                       B + (size_t)(nBase + row) * K + kOff + ldCh * 8);
        }
    };

    issue_stage(0, 0);
    CP_COMMIT();

    const int arow = (lane & 7) + ((lane >> 3) & 1) * 8;
    const int akc8 = (lane >> 4) * 8;
    const int brow = (lane & 7) + ((lane >> 4) & 1) * 8;
    const int bkc8 = ((lane >> 3) & 1) * 8;

    for (int c = 0; c < nch; c++) {
        const int buf = c & 1;
        if (c + 1 < nch) issue_stage(c + 1, (c + 1) & 1);
        CP_COMMIT();
        CP_WAIT1();
        __syncthreads();

        const uint32_t st = sbase + buf * STG4;
        const uint32_t aB = st;
        const uint32_t bB = st + A_BYTES;

#pragma unroll
        for (int s = 0; s < 2; s++) {
            const int kofs = s * 16;
            uint32_t af[4][4];
#pragma unroll
            for (int fm = 0; fm < 4; fm++) {
                const uint32_t off =
                    (uint32_t)((wm * 64 + fm * 16 + arow) * PADB +
                               (kofs + akc8) * 2);
                ldsm_x4(af[fm], aB + off);
            }
#pragma unroll
            for (int bi = 0; bi < 4; bi++) {
                uint32_t bf[4];
                const uint32_t off =
                    (uint32_t)((wn * 64 + bi * 16 + brow) * PADB +
                               (kofs + bkc8) * 2);
                ldsm_x4(bf, bB + off);
#pragma unroll
                for (int fm = 0; fm < 4; fm++) {
                    mma16816(acc[fm][2 * bi],     af[fm], bf);
                    mma16816(acc[fm][2 * bi + 1], af[fm], bf + 2);
                }
            }
        }
        __syncthreads();
    }

    const int r0 = lane >> 2;
    const int c0 = (lane & 3) * 2;
#pragma unroll
    for (int fm = 0; fm < 4; fm++) {
#pragma unroll
        for (int fn = 0; fn < 8; fn++) {
            const size_t row = (size_t)(mBase + wm * 64 + fm * 16 + r0);
            const int col = nBase + wn * 64 + fn * 8 + c0;
            *(float2*)(C + row * N + col) =
                make_float2(acc[fm][fn][0], acc[fm][fn][1]);
            *(float2*)(C + (row + 8) * N + col) =
                make_float2(acc[fm][fn][2], acc[fm][fn][3]);
        }
    }
}

// ---------------------------------------------------------------------------
// Flash attention: single fp16, R14 loop body, but 64 q-rows / 128 threads
// per CTA so TWO CTAs co-reside per SM (89 KB smem each). While one CTA
// runs softmax, the other's MMAs fill the tensor pipe.
// ---------------------------------------------------------------------------
#define FQ_BYTES   (64 * 272)                    // 17408
#define FK_BYTES   (64 * 272)                    // 17408
#define FV_BYTES   (128 * 144)                   // 18432
#define FSTAGE     (FK_BYTES + FV_BYTES)         // 35840
#define FA_SMEM    (FQ_BYTES + 2 * FSTAGE)       // 89088

__global__ __launch_bounds__(128, 2) void flash_mma_kernel(
    const __half* __restrict__ q, const __half* __restrict__ kh,
    const __half* __restrict__ vt, __half* __restrict__ y)
{
    extern __shared__ char smc[];
    const uint32_t sbase = smem_u32(smc);
    const int tid = threadIdx.x;
    const int lane = tid & 31;
    const int wid = tid >> 5;                     // 0..3
    const int b = blockIdx.z, h = blockIdx.y;
    const int bh = b * NH + h;
    const int q0 = blockIdx.x * 64;
    const size_t bT = (size_t)b * TT;
    const int hoff = h * HD;

    // Q load: 64 rows x 16 chunks = 1024 cp.asyncs / 128 threads
    {
#pragma unroll
        for (int i = 0; i < 8; i++) {
            int cid = i * 128 + tid;
            int row = cid >> 4, ch = cid & 15;
            CP_ASYNC16(sbase + row * 272 + ch * 16,
                       q + (bT + q0 + row) * N_EMBD + hoff + ch * 8);
        }
        CP_COMMIT();
    }

    auto issue_stage = [&](int it, int buf) {
        const uint32_t st = sbase + FQ_BYTES + buf * FSTAGE;
        const int n0 = it * 64;
#pragma unroll
        for (int i = 0; i < 8; i++) {
            int cid = i * 128 + tid;
            int row = cid >> 4, ch = cid & 15;
            CP_ASYNC16(st + row * 272 + ch * 16,
                       kh + (bT + n0 + row) * N_EMBD + hoff + ch * 8);
        }
#pragma unroll
        for (int i = 0; i < 8; i++) {
            int cid = i * 128 + tid;
            int row = cid >> 3, ch = cid & 7;
            CP_ASYNC16(st + FK_BYTES + row * 144 + ch * 16,
                       vt + (size_t)(bh * HD + row) * TT + n0 + ch * 8);
        }
    };

    issue_stage(0, 0);
    CP_COMMIT();

    const int arow = (lane & 7) + ((lane >> 3) & 1) * 8;
    const int aoff = (lane >> 4) * 16;
    const int brow = (lane & 7) + ((lane >> 4) & 1) * 8;
    const int boff = ((lane >> 3) & 1) * 16;
    const int g = lane >> 2;
    const int tq = lane & 3;

    float O[16][4];
#pragma unroll
    for (int i = 0; i < 16; i++)
#pragma unroll
        for (int r = 0; r < 4; r++) O[i][r] = 0.0f;
    float ma = -INFINITY, mb = -INFINITY, la = 0.0f, lb = 0.0f;
    const float sc = 0.08838834764831845f;

    const int niter = TT / 64;
    for (int c = 0; c < niter; c++) {
        const int buf = c & 1;
        if (c + 1 < niter) issue_stage(c + 1, (c + 1) & 1);
        CP_COMMIT();
        CP_WAIT1();
        __syncthreads();

        const uint32_t kb = sbase + FQ_BYTES + buf * FSTAGE;

        float s[8][4];
#pragma unroll
        for (int j = 0; j < 8; j++)
#pragma unroll
            for (int r = 0; r < 4; r++) s[j][r] = 0.0f;

#pragma unroll
        for (int kk = 0; kk < 8; kk++) {
            uint32_t qf[4];
            const uint32_t qo = (wid * 16 + arow) * 272 + kk * 32 + aoff;
            ldsm_x4(qf, sbase + qo);
#pragma unroll
            for (int bp = 0; bp < 2; bp++) {
                uint32_t khf[2][4];
#pragma unroll
                for (int u = 0; u < 2; u++) {
                    const int bi = 2 * bp + u;
                    const uint32_t ko = (bi * 16 + brow) * 272 + kk * 32 + boff;
                    ldsm_x4(khf[u], kb + ko);
                }
#pragma unroll
                for (int u = 0; u < 2; u++) {
                    const int bi = 2 * bp + u;
                    mma16816(s[2 * bi],     qf, khf[u]);
                    mma16816(s[2 * bi + 1], qf, khf[u] + 2);
                }
            }
        }

        float mxa = -INFINITY, mxb = -INFINITY;
#pragma unroll
        for (int j = 0; j < 8; j++) {
            s[j][0] *= sc; s[j][1] *= sc; s[j][2] *= sc; s[j][3] *= sc;
            mxa = fmaxf(mxa, fmaxf(s[j][0], s[j][1]));
            mxb = fmaxf(mxb, fmaxf(s[j][2], s[j][3]));
        }
        mxa = fmaxf(mxa, __shfl_xor_sync(0xffffffffu, mxa, 1));
        mxa = fmaxf(mxa, __shfl_xor_sync(0xffffffffu, mxa, 2));
        mxb = fmaxf(mxb, __shfl_xor_sync(0xffffffffu, mxb, 1));
        mxb = fmaxf(mxb, __shfl_xor_sync(0xffffffffu, mxb, 2));
        float mna = fmaxf(ma, mxa), mnb = fmaxf(mb, mxb);
        float alpha = __expf(ma - mna), beta = __expf(mb - mnb);
        ma = mna; mb = mnb;
        float sua = 0.0f, sub = 0.0f;
#pragma unroll
        for (int j = 0; j < 8; j++) {
            s[j][0] = __expf(s[j][0] - mna);
            s[j][1] = __expf(s[j][1] - mna);
            s[j][2] = __expf(s[j][2] - mnb);
            s[j][3] = __expf(s[j][3] - mnb);
            sua += s[j][0] + s[j][1];
            sub += s[j][2] + s[j][3];
        }
        sua += __shfl_xor_sync(0xffffffffu, sua, 1);
        sua += __shfl_xor_sync(0xffffffffu, sua, 2);
        sub += __shfl_xor_sync(0xffffffffu, sub, 1);
        sub += __shfl_xor_sync(0xffffffffu, sub, 2);
        la = la * alpha + sua;
        lb = lb * beta + sub;
#pragma unroll
        for (int j2 = 0; j2 < 16; j2++) {
            O[j2][0] *= alpha; O[j2][1] *= alpha;
            O[j2][2] *= beta;  O[j2][3] *= beta;
        }

        uint32_t Ph[4][4];
#pragma unroll
        for (int kp = 0; kp < 4; kp++) {
            Ph[kp][0] = pack_h(s[2 * kp][0],     s[2 * kp][1]);
            Ph[kp][1] = pack_h(s[2 * kp][2],     s[2 * kp][3]);
            Ph[kp][2] = pack_h(s[2 * kp + 1][0], s[2 * kp + 1][1]);
            Ph[kp][3] = pack_h(s[2 * kp + 1][2], s[2 * kp + 1][3]);
        }

        const uint32_t vb = kb + FK_BYTES;
#pragma unroll
        for (int kp = 0; kp < 4; kp++) {
#pragma unroll
            for (int jp = 0; jp < 4; jp++) {
                uint32_t vhf[2][4];
#pragma unroll
                for (int u = 0; u < 2; u++) {
                    const int j4 = 2 * jp + u;
                    const uint32_t vo = (j4 * 16 + brow) * 144 + kp * 32 + boff;
                    ldsm_x4(vhf[u], vb + vo);
                }
#pragma unroll
                for (int u = 0; u < 2; u++) {
                    const int j4 = 2 * jp + u;
                    mma16816(O[2 * j4],     Ph[kp], vhf[u]);
                    mma16816(O[2 * j4 + 1], Ph[kp], vhf[u] + 2);
                }
            }
        }
        __syncthreads();
    }

    // ---- epilogue ----
    const float inva = 1.0f / la, invb = 1.0f / lb;
    const size_t rowa = bT + q0 + wid * 16 + g;
    const size_t rowb = rowa + 8;
#pragma unroll
    for (int j2 = 0; j2 < 16; j2++) {
        const int col = hoff + j2 * 8 + tq * 2;
        *(uint32_t*)(y + rowa * N_EMBD + col) =
            pack_h(O[j2][0] * inva, O[j2][1] * inva);
        *(uint32_t*)(y + rowb * N_EMBD + col) =
            pack_h(O[j2][2] * invb, O[j2][3] * invb);
    }
}

// ---------------------------------------------------------------------------
// Launch
// ---------------------------------------------------------------------------
extern "C" void kernel_launch(void* const* d_in, const int* in_sizes, int n_in,
                              void* d_out, int out_size)
{
    const float* x      = (const float*)d_in[0];
    const float* w_attn = (const float*)d_in[1];
    const float* w_proj = (const float*)d_in[2];
    float* out = (float*)d_out;

    __half *A, *Wa, *Wp, *Q, *Kb, *Vh, *Vt;
    cudaGetSymbolAddress((void**)&A, g_A);
    cudaGetSymbolAddress((void**)&Wa, g_Wa);
    cudaGetSymbolAddress((void**)&Wp, g_Wp);
    cudaGetSymbolAddress((void**)&Q, g_Q);
    cudaGetSymbolAddress((void**)&Kb, g_K);
    cudaGetSymbolAddress((void**)&Vh, g_Vh);
    cudaGetSymbolAddress((void**)&Vt, g_Vt);

    cudaFuncSetAttribute(gemm_qkv_kernel,
                         cudaFuncAttributeMaxDynamicSharedMemorySize, QKV_SMEM);
    cudaFuncSetAttribute(gemm_proj_kernel,
                         cudaFuncAttributeMaxDynamicSharedMemorySize, PROJ_SMEM);
    cudaFuncSetAttribute(flash_mma_kernel,
                         cudaFuncAttributeMaxDynamicSharedMemorySize, FA_SMEM);

    const int n4 = MROWS * N_EMBD / 4;

    rope_table_kernel<<<(TT * 64 + 255) / 256, 256>>>();

    conv_single_kernel<<<(n4 + 255) / 256, 256>>>(x, A, n4);
    conv_tr_kernel<<<dim3(QKV_N / 32, N_EMBD / 32), dim3(32, 8)>>>(
        w_attn, Wa, N_EMBD, QKV_N);
    conv_tr_kernel<<<dim3(N_EMBD / 32, N_EMBD / 32), dim3(32, 8)>>>(
        w_proj, Wp, N_EMBD, N_EMBD);

    gemm_qkv_kernel<<<dim3(QKV_N / BN6, MROWS / BM), 256, QKV_SMEM>>>(
        A, Wa, Q, Kb, Vh);

    conv_vth_kernel<<<dim3(TT / 32, HD / 32, BB * NH), dim3(32, 8)>>>(Vh, Vt);

    // Flash: 64 q-rows per CTA, 128 threads, 2 CTAs/SM
    flash_mma_kernel<<<dim3(TT / 64, NH, BB), 128, FA_SMEM>>>(
        Q, Kb, Vt, A);

    gemm_proj_kernel<<<dim3(N_EMBD / BN4, MROWS / BM), 256, PROJ_SMEM>>>(
        A, Wp, out, MROWS, N_EMBD, N_EMBD);
}